// round 1
// baseline (speedup 1.0000x reference)
#include <cuda_runtime.h>
#include <math.h>

#define BB 4
#define SS 4096
#define HH 8
#define DD 64
#define HD (HH*DD)
#define SCALE 0.125f

// Tree node storage for levels 1..11 (padded to 4096 node slots per (b,h)).
// Node layout: [B*H][4096][64] floats.
__device__ float g_treeK[(size_t)BB*HH*4096*DD];
__device__ float g_treeV[(size_t)BB*HH*4096*DD];

__device__ __forceinline__ int toff(int l) {            // offset of level l (l>=1)
    return SS - (SS >> (l - 1));                        // l=1 -> 0, l=2 -> 2048, ...
}

// Softmax-pool two children (each lane holds 2 dims). Warp-collective.
__device__ __forceinline__ void pool(float2 kc0, float2 kc1, float2 vc0, float2 vc1,
                                     float2& kp, float2& vp) {
    kp.x = 0.5f * (kc0.x + kc1.x);
    kp.y = 0.5f * (kc0.y + kc1.y);
    float ds = kp.x * kp.x + kp.y * kp.y;
    float d0 = kp.x * kc0.x + kp.y * kc0.y;
    float d1 = kp.x * kc1.x + kp.y * kc1.y;
#pragma unroll
    for (int o = 16; o; o >>= 1) {
        ds += __shfl_xor_sync(0xffffffffu, ds, o);
        d0 += __shfl_xor_sync(0xffffffffu, d0, o);
        d1 += __shfl_xor_sync(0xffffffffu, d1, o);
    }
    float ss = ds * SCALE, s0 = d0 * SCALE, s1 = d1 * SCALE;
    float m  = fmaxf(ss, fmaxf(s0, s1));
    float es = __expf(ss - m), e0 = __expf(s0 - m), e1 = __expf(s1 - m);
    float inv = 1.0f / (es + e0 + e1 + 1e-9f);
    float hes = 0.5f * es;
    vp.x = (hes * (vc0.x + vc1.x) + e0 * vc0.x + e1 * vc1.x) * inv;
    vp.y = (hes * (vc0.y + vc1.y) + e0 * vc0.y + e1 * vc1.y) * inv;
}

// Build tree levels 1..7. One block per 128-leaf chunk of one (b,h).
__global__ __launch_bounds__(1024) void build_low(const float* __restrict__ k,
                                                  const float* __restrict__ v) {
    int blk   = blockIdx.x;
    int chunk = blk & 31;          // 32 chunks of 128 leaves per (b,h)
    int bh    = blk >> 5;          // b*H + h
    int b = bh >> 3, h = bh & 7;
    int warp = threadIdx.x >> 5, lane = threadIdx.x & 31;
    size_t treebase = (size_t)bh * 4096 * DD + 2 * lane;

    // Level 1: 64 parents per chunk, leaves come from global k/v (B,S,H,D).
#pragma unroll
    for (int p = warp; p < 64; p += 32) {
        int j = chunk * 64 + p;    // within-level index at level 1
        size_t c0 = ((size_t)(b * SS + 2 * j) * HH + h) * DD + 2 * lane;
        size_t c1 = c0 + HD;
        float2 kc0 = *(const float2*)(k + c0);
        float2 kc1 = *(const float2*)(k + c1);
        float2 vc0 = *(const float2*)(v + c0);
        float2 vc1 = *(const float2*)(v + c1);
        float2 kp, vp;
        pool(kc0, kc1, vc0, vc1, kp, vp);
        size_t po = treebase + (size_t)j * DD;   // toff(1)==0
        *(float2*)(g_treeK + po) = kp;
        *(float2*)(g_treeV + po) = vp;
    }

    // Levels 2..7 (children read back from global; __syncthreads makes the
    // block's prior global writes visible to the block).
#pragma unroll
    for (int l = 2; l <= 7; l++) {
        __syncthreads();
        int cnt = 64 >> (l - 1);   // parents per chunk at level l
        if (warp < cnt) {
            int j = chunk * cnt + warp;               // within-level index
            size_t c0 = treebase + (size_t)(toff(l - 1) + 2 * j) * DD;
            size_t c1 = c0 + DD;
            float2 kc0 = *(const float2*)(g_treeK + c0);
            float2 kc1 = *(const float2*)(g_treeK + c1);
            float2 vc0 = *(const float2*)(g_treeV + c0);
            float2 vc1 = *(const float2*)(g_treeV + c1);
            float2 kp, vp;
            pool(kc0, kc1, vc0, vc1, kp, vp);
            size_t po = treebase + (size_t)(toff(l) + j) * DD;
            *(float2*)(g_treeK + po) = kp;
            *(float2*)(g_treeV + po) = vp;
        }
    }
}

// Build tree levels 8..11. One block per (b,h).
__global__ __launch_bounds__(512) void build_high() {
    int bh   = blockIdx.x;
    int warp = threadIdx.x >> 5, lane = threadIdx.x & 31;
    size_t treebase = (size_t)bh * 4096 * DD + 2 * lane;

#pragma unroll
    for (int l = 8; l <= 11; l++) {
        __syncthreads();
        int cnt = SS >> l;         // 16, 8, 4, 2
        if (warp < cnt) {
            int j = warp;
            size_t c0 = treebase + (size_t)(toff(l - 1) + 2 * j) * DD;
            size_t c1 = c0 + DD;
            float2 kc0 = *(const float2*)(g_treeK + c0);
            float2 kc1 = *(const float2*)(g_treeK + c1);
            float2 vc0 = *(const float2*)(g_treeV + c0);
            float2 vc1 = *(const float2*)(g_treeV + c1);
            float2 kp, vp;
            pool(kc0, kc1, vc0, vc1, kp, vp);
            size_t po = treebase + (size_t)(toff(l) + j) * DD;
            *(float2*)(g_treeK + po) = kp;
            *(float2*)(g_treeV + po) = vp;
        }
    }
}

// Attention: one warp per query, online softmax over <=13 keys.
__global__ __launch_bounds__(1024) void attn(const float* __restrict__ q,
                                             const float* __restrict__ k,
                                             const float* __restrict__ v,
                                             float* __restrict__ out) {
    int warp = threadIdx.x >> 5, lane = threadIdx.x & 31;
    int qi = blockIdx.x * 32 + warp;         // ((b*H + h)*S + s)
    int s  = qi & (SS - 1);
    int bh = qi >> 12;
    int b = bh >> 3, h = bh & 7;

    size_t qoff = ((size_t)(b * SS + s) * HH + h) * DD + 2 * lane;
    float2 qv = *(const float2*)(q + qoff);
    size_t treebase = (size_t)bh * 4096 * DD + 2 * lane;

    float m, denom;
    float2 acc;

    // self term
    {
        float2 kv = *(const float2*)(k + qoff);
        float2 vv = *(const float2*)(v + qoff);
        float d = qv.x * kv.x + qv.y * kv.y;
#pragma unroll
        for (int o = 16; o; o >>= 1) d += __shfl_xor_sync(0xffffffffu, d, o);
        m = d * SCALE;
        denom = 1.0f;
        acc = vv;
    }

    auto process = [&](const float* __restrict__ kp, const float* __restrict__ vp) {
        float2 kv = *(const float2*)kp;
        float2 vv = *(const float2*)vp;
        float d = qv.x * kv.x + qv.y * kv.y;
#pragma unroll
        for (int o = 16; o; o >>= 1) d += __shfl_xor_sync(0xffffffffu, d, o);
        float sc = d * SCALE;
        float mn = fmaxf(m, sc);
        float c  = __expf(m - mn);
        float w  = __expf(sc - mn);
        denom = denom * c + w;
        acc.x = acc.x * c + w * vv.x;
        acc.y = acc.y * c + w * vv.y;
        m = mn;
    };

    // level 0: left sibling leaf
    if (s & 1) {
        size_t off = qoff - HD;
        process(k + off, v + off);
    }
    // levels 1..11: left sibling of the level-l ancestor when bit l is set
#pragma unroll
    for (int l = 1; l <= 11; l++) {
        if ((s >> l) & 1) {
            int node = toff(l) + (s >> l) - 1;
            size_t off = treebase + (size_t)node * DD;
            process(g_treeK + off, g_treeV + off);
        }
    }

    float inv = 1.0f / denom;
    float2 o2;
    o2.x = acc.x * inv;
    o2.y = acc.y * inv;
    *(float2*)(out + qoff) = o2;
}

extern "C" void kernel_launch(void* const* d_in, const int* in_sizes, int n_in,
                              void* d_out, int out_size) {
    const float* q = (const float*)d_in[0];
    const float* k = (const float*)d_in[1];
    const float* v = (const float*)d_in[2];
    float* out = (float*)d_out;

    build_low<<<BB * HH * 32, 1024>>>(k, v);
    build_high<<<BB * HH, 512>>>();
    attn<<<(BB * HH * SS) / 32, 1024>>>(q, k, v, out);
}